// round 15
// baseline (speedup 1.0000x reference)
#include <cuda_runtime.h>
#include <cuda_fp16.h>
#include <cstdint>
#include <math.h>

#define NS 8192
#define NE 8192
#define HH 512
#define PP 64
#define KC 128              // fp16 concat K = [hi(64) | lo(64)]

// fp16 split operands: [N, 128] row-major (256B per row).
__device__ __half g_sub_cat[(size_t)NS * KC];
__device__ __half g_edge_cat[(size_t)NE * KC];

__device__ __forceinline__ uint32_t smem_u32(const void* p) {
    uint32_t a;
    asm("{ .reg .u64 t; cvta.to.shared.u64 t, %1; cvt.u32.u64 %0, t; }" : "=r"(a) : "l"(p));
    return a;
}
__device__ __forceinline__ void ldmx4(uint32_t* r, uint32_t addr) {
    asm volatile("ldmatrix.sync.aligned.m8n8.x4.shared.b16 {%0,%1,%2,%3}, [%4];"
                 : "=r"(r[0]), "=r"(r[1]), "=r"(r[2]), "=r"(r[3]) : "r"(addr));
}
__device__ __forceinline__ void mma_f32(float* d, const uint32_t* a, const uint32_t* b) {
    asm volatile(
        "mma.sync.aligned.m16n8k16.row.col.f32.f16.f16.f32 "
        "{%0,%1,%2,%3}, {%4,%5,%6,%7}, {%8,%9}, {%0,%1,%2,%3};"
        : "+f"(d[0]), "+f"(d[1]), "+f"(d[2]), "+f"(d[3])
        : "r"(a[0]), "r"(a[1]), "r"(a[2]), "r"(a[3]), "r"(b[0]), "r"(b[1]));
}
__device__ __forceinline__ void mma_f16(uint32_t* d, const uint32_t* a, const uint32_t* b) {
    asm volatile(
        "mma.sync.aligned.m16n8k16.row.col.f16.f16.f16.f16 "
        "{%0,%1}, {%2,%3,%4,%5}, {%6,%7}, {%0,%1};"
        : "+r"(d[0]), "+r"(d[1])
        : "r"(a[0]), "r"(a[1]), "r"(a[2]), "r"(a[3]), "r"(b[0]), "r"(b[1]));
}
__device__ __forceinline__ void cpa16(uint32_t s, const void* g) {
    asm volatile("cp.async.cg.shared.global [%0], [%1], 16;" :: "r"(s), "l"(g) : "memory");
}

// ---------------------------------------------------------------------------
// proj: out = l2_normalize(X @ W^T + b) -> fp16 hi/lo [N,128].
// 64x64 tile, 8x4 microtile, 128 threads (ratio 2.67 FMA/LDS-float; ~5 CTAs/SM).
// K=512 in 8 chunks of 64, transposed smem. blockIdx.y: 0=sub, 1=edge.
// ---------------------------------------------------------------------------
__global__ __launch_bounds__(128) void proj_kernel(const float* __restrict__ Xs_in,
                                                   const float* __restrict__ Xe_in,
                                                   const float* __restrict__ Ws_in,
                                                   const float* __restrict__ bs_in,
                                                   const float* __restrict__ We_in,
                                                   const float* __restrict__ be_in)
{
    __shared__ float Xs[64 * 64];   // [k][row]
    __shared__ float Ws[64 * 64];   // [k][col]

    const int which = blockIdx.y;
    const float4* X4 = reinterpret_cast<const float4*>(which ? Xe_in : Xs_in);
    const float4* W4 = reinterpret_cast<const float4*>(which ? We_in : Ws_in);
    const float*  bb = which ? be_in : bs_in;
    __half* out = which ? g_edge_cat : g_sub_cat;

    const int tid = threadIdx.x;
    const int tx = tid & 15;        // 16 col groups of 4
    const int ty = tid >> 4;        // 8 row groups of 8
    const int rbase = blockIdx.x * 64;

    float acc[8][4];
#pragma unroll
    for (int i = 0; i < 8; i++)
#pragma unroll
        for (int j = 0; j < 4; j++) acc[i][j] = 0.f;

#pragma unroll 1
    for (int kc = 0; kc < 8; kc++) {
        if (kc) __syncthreads();
        // X chunk: 64 rows x 16 float4 = 1024 (8/thread); W same.
#pragma unroll
        for (int it = 0; it < 8; it++) {
            int t = tid + it * 128;      // 0..1023
            int row = t & 63;
            int q   = t >> 6;            // 0..15
            float4 vx = X4[(size_t)(rbase + row) * 128 + kc * 16 + q];
            Xs[(4 * q + 0) * 64 + row] = vx.x; Xs[(4 * q + 1) * 64 + row] = vx.y;
            Xs[(4 * q + 2) * 64 + row] = vx.z; Xs[(4 * q + 3) * 64 + row] = vx.w;
            float4 vw = W4[(size_t)row * 128 + kc * 16 + q];
            Ws[(4 * q + 0) * 64 + row] = vw.x; Ws[(4 * q + 1) * 64 + row] = vw.y;
            Ws[(4 * q + 2) * 64 + row] = vw.z; Ws[(4 * q + 3) * 64 + row] = vw.w;
        }
        __syncthreads();
#pragma unroll
        for (int k = 0; k < 64; k++) {
            float4 a0 = *reinterpret_cast<const float4*>(&Xs[k * 64 + ty * 8]);
            float4 a1 = *reinterpret_cast<const float4*>(&Xs[k * 64 + ty * 8 + 4]);
            float4 bv = *reinterpret_cast<const float4*>(&Ws[k * 64 + tx * 4]);
            const float av[8] = {a0.x, a0.y, a0.z, a0.w, a1.x, a1.y, a1.z, a1.w};
            const float bw[4] = {bv.x, bv.y, bv.z, bv.w};
#pragma unroll
            for (int i = 0; i < 8; i++)
#pragma unroll
                for (int j = 0; j < 4; j++)
                    acc[i][j] = fmaf(av[i], bw[j], acc[i][j]);
        }
    }

    // bias
#pragma unroll
    for (int j = 0; j < 4; j++) {
        float bj = bb[tx * 4 + j];
#pragma unroll
        for (int i = 0; i < 8; i++) acc[i][j] += bj;
    }

    // row L2 norms (reduce across 16 tx threads; tx = lane bits 0..3)
#pragma unroll
    for (int i = 0; i < 8; i++) {
        float rs = acc[i][0] * acc[i][0] + acc[i][1] * acc[i][1]
                 + acc[i][2] * acc[i][2] + acc[i][3] * acc[i][3];
#pragma unroll
        for (int off = 1; off < 16; off <<= 1)
            rs += __shfl_xor_sync(0xffffffffu, rs, off);
        float inv = 1.0f / fmaxf(sqrtf(rs), 1e-12f);

        int row = rbase + ty * 8 + i;
        __half h[4], l[4];
#pragma unroll
        for (int j = 0; j < 4; j++) {
            float v = acc[i][j] * inv;
            h[j] = __float2half(v);
            l[j] = __float2half(v - __half2float(h[j]));
        }
        uint2 hp, lp;
        hp.x = ((uint32_t)__half_as_ushort(h[1]) << 16) | __half_as_ushort(h[0]);
        hp.y = ((uint32_t)__half_as_ushort(h[3]) << 16) | __half_as_ushort(h[2]);
        lp.x = ((uint32_t)__half_as_ushort(l[1]) << 16) | __half_as_ushort(l[0]);
        lp.y = ((uint32_t)__half_as_ushort(l[3]) << 16) | __half_as_ushort(l[2]);
        *reinterpret_cast<uint2*>(&out[(size_t)row * KC + tx * 4])      = hp;
        *reinterpret_cast<uint2*>(&out[(size_t)row * KC + 64 + tx * 4]) = lp;
    }
}

// ---------------------------------------------------------------------------
// scores GEMM: 128x64 tile/CTA. K=128 fp16 [hi|lo] loaded once (48KB smem).
// hi*hi -> f32 accum;  hi*lo + lo*hi -> f16 accum (magnitude ~2^-12).
// (R12 verbatim.)
// ---------------------------------------------------------------------------
__global__ __launch_bounds__(256, 2) void scores_mma_kernel(const float* __restrict__ log_scale,
                                                            float* __restrict__ out)
{
    __shared__ char smem[49152];
    const uint32_t sA = smem_u32(smem);     // 32KB: 256 swizzle-rows of 128B
    const uint32_t sB = sA + 32768;         // 16KB: 128 swizzle-rows

    const int tid  = threadIdx.x;
    const int wid  = tid >> 5;
    const int lane = tid & 31;
    const int wm = wid & 3;        // 4 warps along M (32 each)
    const int wn = wid >> 2;       // 2 warps along N (32 each)
    const int brow = blockIdx.y * 128;
    const int bcol = blockIdx.x * 64;

    const char* gA = reinterpret_cast<const char*>(g_sub_cat);
    const char* gB = reinterpret_cast<const char*>(g_edge_cat);

#pragma unroll
    for (int it = 0; it < 8; it++) {
        int qi = tid + it * 256;
        int sr = qi >> 3, lq = qi & 7;
        int r = sr & 127, c = sr >> 7;
        cpa16(sA + sr * 128 + ((lq ^ (sr & 7)) << 4),
              gA + (size_t)(brow + r) * 256 + c * 128 + lq * 16);
    }
#pragma unroll
    for (int it = 0; it < 4; it++) {
        int qi = tid + it * 256;
        int sr = qi >> 3, lq = qi & 7;
        int r = sr & 63, c = sr >> 6;
        cpa16(sB + sr * 128 + ((lq ^ (sr & 7)) << 4),
              gB + (size_t)(bcol + r) * 256 + c * 128 + lq * 16);
    }
    asm volatile("cp.async.commit_group;" ::: "memory");
    asm volatile("cp.async.wait_group 0;" ::: "memory");
    __syncthreads();

    float    accf[2][4][4];
    uint32_t acch[2][4][2];
#pragma unroll
    for (int mt = 0; mt < 2; mt++)
#pragma unroll
        for (int nt = 0; nt < 4; nt++) {
#pragma unroll
            for (int q = 0; q < 4; q++) accf[mt][nt][q] = 0.f;
            acch[mt][nt][0] = 0u; acch[mt][nt][1] = 0u;
        }

    const int g  = lane >> 3;
    const int rl = lane & 7;
    const int gl = g & 1;
    const int gh = g >> 1;

    uint32_t aOff[2][2];   // [chunk][mt]
#pragma unroll
    for (int ca = 0; ca < 2; ca++)
#pragma unroll
        for (int mt = 0; mt < 2; mt++)
            aOff[ca][mt] = sA + (uint32_t)(ca * 128 + wm * 32 + mt * 16 + rl + gl * 8) * 128u;
    uint32_t bOff[2][2];   // [chunk][pn]
#pragma unroll
    for (int cb = 0; cb < 2; cb++)
#pragma unroll
        for (int pn = 0; pn < 2; pn++)
            bOff[cb][pn] = sB + (uint32_t)(cb * 64 + wn * 32 + pn * 16 + rl + gh * 8) * 128u;

#pragma unroll
    for (int s = 0; s < 4; s++) {
        const uint32_t ca_col = (uint32_t)(((2 * s + gh) ^ rl) << 4);
        const uint32_t cb_col = (uint32_t)(((2 * s + gl) ^ rl) << 4);
        uint32_t a0[2][4], a1[2][4], b0[2][4], b1[2][4];
#pragma unroll
        for (int mt = 0; mt < 2; mt++) {
            ldmx4(a0[mt], aOff[0][mt] + ca_col);   // hi
            ldmx4(a1[mt], aOff[1][mt] + ca_col);   // lo
        }
#pragma unroll
        for (int pn = 0; pn < 2; pn++) {
            ldmx4(b0[pn], bOff[0][pn] + cb_col);   // hi
            ldmx4(b1[pn], bOff[1][pn] + cb_col);   // lo
        }
#pragma unroll
        for (int mt = 0; mt < 2; mt++)
#pragma unroll
            for (int pn = 0; pn < 2; pn++) {
                mma_f32(accf[mt][2 * pn],     a0[mt], &b0[pn][0]);
                mma_f32(accf[mt][2 * pn + 1], a0[mt], &b0[pn][2]);
                mma_f16(acch[mt][2 * pn],     a0[mt], &b1[pn][0]);
                mma_f16(acch[mt][2 * pn + 1], a0[mt], &b1[pn][2]);
                mma_f16(acch[mt][2 * pn],     a1[mt], &b0[pn][0]);
                mma_f16(acch[mt][2 * pn + 1], a1[mt], &b0[pn][2]);
            }
    }

    const float zs = 0.5f * fminf(fmaxf(expf(*log_scale), 0.5f), 20.0f);

    const int r0 = brow + wm * 32 + (lane >> 2);
    const int c0 = bcol + wn * 32 + 2 * (lane & 3);
#pragma unroll
    for (int mt = 0; mt < 2; mt++)
#pragma unroll
        for (int nt = 0; nt < 4; nt++) {
            float2 c01 = __half22float2(*reinterpret_cast<__half2*>(&acch[mt][nt][0]));
            float2 c23 = __half22float2(*reinterpret_cast<__half2*>(&acch[mt][nt][1]));
            float* p0 = out + (size_t)(r0 + mt * 16) * NE + c0 + nt * 8;
            float* p1 = p0 + 8 * NE;
            *reinterpret_cast<float2*>(p0) =
                make_float2((accf[mt][nt][0] + c01.x) * zs, (accf[mt][nt][1] + c01.y) * zs);
            *reinterpret_cast<float2*>(p1) =
                make_float2((accf[mt][nt][2] + c23.x) * zs, (accf[mt][nt][3] + c23.y) * zs);
        }
}

// ---------------------------------------------------------------------------
// entmax-1.5 per row, in place. Pass 0: support-quadratic jump from tau0=max-1
// (proven). Then secant on h(tau)=sqrt(S2)-1 (only S2 per pass). Stopping
// loosened to |h| < 2e-5: ||dp|| = 2*dtau*sqrt(S2) <= 4e-5, >=25x margin
// under the 1e-3 rel-err threshold; saves the superlinear tail passes.
// ---------------------------------------------------------------------------
__global__ __launch_bounds__(256) void entmax_kernel(float* __restrict__ out)
{
    __shared__ float s1[8], s2[2][8], sc[8], smax[8];

    const int tid  = threadIdx.x;
    const int lane = tid & 31;
    const int warp = tid >> 5;
    float4* row = reinterpret_cast<float4*>(out + (size_t)blockIdx.x * NE);

    float4 v[8];
#pragma unroll
    for (int j = 0; j < 8; j++) v[j] = row[tid + 256 * j];

    float m = -3.4e38f;
#pragma unroll
    for (int j = 0; j < 8; j++)
        m = fmaxf(m, fmaxf(fmaxf(v[j].x, v[j].y), fmaxf(v[j].z, v[j].w)));
#pragma unroll
    for (int off = 16; off > 0; off >>= 1)
        m = fmaxf(m, __shfl_xor_sync(0xffffffffu, m, off));
    if (lane == 0) smax[warp] = m;
    __syncthreads();
    float mm = smax[0];
#pragma unroll
    for (int w = 1; w < 8; w++) mm = fmaxf(mm, smax[w]);

    const float tlo = mm - 1.0f;
    const float thi = mm - 0.011048543f;   // tau* <= max - 1/sqrt(8192)
    float tau = tlo;
    float t_prev = tlo, h_prev = 0.f;

    // ---- pass 0: (S1, S2, C) at tau0; support-quadratic jump; record h0
    {
        float a = 0.f, q = 0.f, cn = 0.f;
#pragma unroll
        for (int j = 0; j < 8; j++) {
            float d;
            d = v[j].x - tau; if (d > 0.f) { a += d; q = fmaf(d, d, q); cn += 1.f; }
            d = v[j].y - tau; if (d > 0.f) { a += d; q = fmaf(d, d, q); cn += 1.f; }
            d = v[j].z - tau; if (d > 0.f) { a += d; q = fmaf(d, d, q); cn += 1.f; }
            d = v[j].w - tau; if (d > 0.f) { a += d; q = fmaf(d, d, q); cn += 1.f; }
        }
#pragma unroll
        for (int off = 16; off > 0; off >>= 1) {
            a  += __shfl_xor_sync(0xffffffffu, a,  off);
            q  += __shfl_xor_sync(0xffffffffu, q,  off);
            cn += __shfl_xor_sync(0xffffffffu, cn, off);
        }
        if (lane == 0) { s1[warp] = a; s2[0][warp] = q; sc[warp] = cn; }
        __syncthreads();
        float S1 = 0.f, S2 = 0.f, C = 0.f;
#pragma unroll
        for (int w = 0; w < 8; w++) { S1 += s1[w]; S2 += s2[0][w]; C += sc[w]; }
        h_prev = sqrtf(S2) - 1.0f;
        if (C >= 1.f && S1 > 0.f && h_prev > 1e-7f) {
            float err  = S2 - 1.0f;
            float disc = S1 * S1 - C * err;
            float dt   = (disc > 0.f) ? (S1 - sqrtf(disc)) / C
                                      : (S2 - sqrtf(S2)) / S1;
            tau = fminf(tau + dt, thi);
        }
    }

    // ---- secant on h(tau) = sqrt(S2(tau)) - 1 (only S2 per pass)
#pragma unroll 1
    for (int it = 1; it < 24; it++) {
        const int p = it & 1;
        float q = 0.f;
#pragma unroll
        for (int j = 0; j < 8; j++) {
            float d;
            d = fmaxf(v[j].x - tau, 0.f); q = fmaf(d, d, q);
            d = fmaxf(v[j].y - tau, 0.f); q = fmaf(d, d, q);
            d = fmaxf(v[j].z - tau, 0.f); q = fmaf(d, d, q);
            d = fmaxf(v[j].w - tau, 0.f); q = fmaf(d, d, q);
        }
#pragma unroll
        for (int off = 16; off > 0; off >>= 1)
            q += __shfl_xor_sync(0xffffffffu, q, off);
        if (lane == 0) s2[p][warp] = q;
        __syncthreads();
        float S2 = 0.f;
#pragma unroll
        for (int w = 0; w < 8; w++) S2 += s2[p][w];

        float h = sqrtf(S2) - 1.0f;
        if (fabsf(h) < 2e-5f) break;
        float denom = h - h_prev;
        if (fabsf(denom) < 1e-12f) break;
        float dt = -h * (tau - t_prev) / denom;
        t_prev = tau; h_prev = h;
        tau = fminf(fmaxf(tau + dt, tlo), thi);
        if (fabsf(dt) < 1e-6f) break;
    }

#pragma unroll
    for (int j = 0; j < 8; j++) {
        float4 o;
        float d;
        d = fmaxf(v[j].x - tau, 0.f); o.x = d * d;
        d = fmaxf(v[j].y - tau, 0.f); o.y = d * d;
        d = fmaxf(v[j].z - tau, 0.f); o.z = d * d;
        d = fmaxf(v[j].w - tau, 0.f); o.w = d * d;
        row[tid + 256 * j] = o;
    }
}

// ---------------------------------------------------------------------------
extern "C" void kernel_launch(void* const* d_in, const int* in_sizes, int n_in,
                              void* d_out, int out_size)
{
    const float* edge_repr = (const float*)d_in[0];
    const float* sub_repr  = (const float*)d_in[1];
    const float* W_sub     = (const float*)d_in[2];
    const float* b_sub     = (const float*)d_in[3];
    const float* W_edge    = (const float*)d_in[4];
    const float* b_edge    = (const float*)d_in[5];
    const float* log_scale = (const float*)d_in[6];
    float* out = (float*)d_out;

    proj_kernel<<<dim3(NS / 64, 2), 128>>>(sub_repr, edge_repr,
                                           W_sub, b_sub, W_edge, b_edge);

    dim3 grid(NE / 64, NS / 128);
    scores_mma_kernel<<<grid, 256>>>(log_scale, out);

    entmax_kernel<<<NS, 256>>>(out);
}

// round 16
// speedup vs baseline: 1.0560x; 1.0560x over previous
#include <cuda_runtime.h>
#include <cuda_fp16.h>
#include <cstdint>
#include <math.h>

#define NS 8192
#define NE 8192
#define HH 512
#define PP 64
#define KC 128              // fp16 concat K = [hi(64) | lo(64)]

// fp16 split operands: [N, 128] row-major (256B per row).
__device__ __half g_sub_cat[(size_t)NS * KC];
__device__ __half g_edge_cat[(size_t)NE * KC];

__device__ __forceinline__ uint32_t smem_u32(const void* p) {
    uint32_t a;
    asm("{ .reg .u64 t; cvta.to.shared.u64 t, %1; cvt.u32.u64 %0, t; }" : "=r"(a) : "l"(p));
    return a;
}
__device__ __forceinline__ void ldmx4(uint32_t* r, uint32_t addr) {
    asm volatile("ldmatrix.sync.aligned.m8n8.x4.shared.b16 {%0,%1,%2,%3}, [%4];"
                 : "=r"(r[0]), "=r"(r[1]), "=r"(r[2]), "=r"(r[3]) : "r"(addr));
}
__device__ __forceinline__ void mma_f32(float* d, const uint32_t* a, const uint32_t* b) {
    asm volatile(
        "mma.sync.aligned.m16n8k16.row.col.f32.f16.f16.f32 "
        "{%0,%1,%2,%3}, {%4,%5,%6,%7}, {%8,%9}, {%0,%1,%2,%3};"
        : "+f"(d[0]), "+f"(d[1]), "+f"(d[2]), "+f"(d[3])
        : "r"(a[0]), "r"(a[1]), "r"(a[2]), "r"(a[3]), "r"(b[0]), "r"(b[1]));
}
__device__ __forceinline__ void mma_f16(uint32_t* d, const uint32_t* a, const uint32_t* b) {
    asm volatile(
        "mma.sync.aligned.m16n8k16.row.col.f16.f16.f16.f16 "
        "{%0,%1}, {%2,%3,%4,%5}, {%6,%7}, {%0,%1};"
        : "+r"(d[0]), "+r"(d[1])
        : "r"(a[0]), "r"(a[1]), "r"(a[2]), "r"(a[3]), "r"(b[0]), "r"(b[1]));
}
__device__ __forceinline__ void cpa16(uint32_t s, const void* g) {
    asm volatile("cp.async.cg.shared.global [%0], [%1], 16;" :: "r"(s), "l"(g) : "memory");
}

// ---------------------------------------------------------------------------
// proj: out = l2_normalize(X @ W^T + b) -> fp16 hi/lo [N,128].
// R6 version verbatim (measured 52us three times — grid-limited equilibrium).
// CTA: 64 rows x 64 cols, 4x4 microtile, 256 threads, K=512 in 8 chunks.
// ---------------------------------------------------------------------------
__global__ __launch_bounds__(256) void proj_kernel(const float* __restrict__ Xs_in,
                                                   const float* __restrict__ Xe_in,
                                                   const float* __restrict__ Ws_in,
                                                   const float* __restrict__ bs_in,
                                                   const float* __restrict__ We_in,
                                                   const float* __restrict__ be_in)
{
    __shared__ float Xs[64 * 64];   // [k][row]
    __shared__ float Ws[64 * 64];   // [k][col]

    const int which = blockIdx.y;
    const float4* X4 = reinterpret_cast<const float4*>(which ? Xe_in : Xs_in);
    const float4* W4 = reinterpret_cast<const float4*>(which ? We_in : Ws_in);
    const float*  bb = which ? be_in : bs_in;
    __half* out = which ? g_edge_cat : g_sub_cat;

    const int tid = threadIdx.x;
    const int tx = tid & 15;
    const int ty = tid >> 4;
    const int rbase = blockIdx.x * 64;

    float acc[4][4];
#pragma unroll
    for (int i = 0; i < 4; i++)
#pragma unroll
        for (int j = 0; j < 4; j++) acc[i][j] = 0.f;

#pragma unroll 1
    for (int kc = 0; kc < 8; kc++) {
        if (kc) __syncthreads();
#pragma unroll
        for (int it = 0; it < 4; it++) {
            int t = tid + it * 256;      // 0..1023
            int row = t & 63;
            int q   = t >> 6;            // 0..15 (float4 within 64-float chunk)
            float4 vx = X4[(size_t)(rbase + row) * 128 + kc * 16 + q];
            Xs[(4 * q + 0) * 64 + row] = vx.x; Xs[(4 * q + 1) * 64 + row] = vx.y;
            Xs[(4 * q + 2) * 64 + row] = vx.z; Xs[(4 * q + 3) * 64 + row] = vx.w;
            float4 vw = W4[(size_t)row * 128 + kc * 16 + q];
            Ws[(4 * q + 0) * 64 + row] = vw.x; Ws[(4 * q + 1) * 64 + row] = vw.y;
            Ws[(4 * q + 2) * 64 + row] = vw.z; Ws[(4 * q + 3) * 64 + row] = vw.w;
        }
        __syncthreads();
#pragma unroll
        for (int k = 0; k < 64; k++) {
            float4 a  = *reinterpret_cast<const float4*>(&Xs[k * 64 + ty * 4]);
            float4 bv = *reinterpret_cast<const float4*>(&Ws[k * 64 + tx * 4]);
            const float av[4] = {a.x, a.y, a.z, a.w};
            const float bw[4] = {bv.x, bv.y, bv.z, bv.w};
#pragma unroll
            for (int i = 0; i < 4; i++)
#pragma unroll
                for (int j = 0; j < 4; j++)
                    acc[i][j] = fmaf(av[i], bw[j], acc[i][j]);
        }
    }

    // bias
#pragma unroll
    for (int j = 0; j < 4; j++) {
        float bj = bb[tx * 4 + j];
#pragma unroll
        for (int i = 0; i < 4; i++) acc[i][j] += bj;
    }

    // row L2 norms (reduce across 16 tx threads; tx bits = lane bits 0..3)
#pragma unroll
    for (int i = 0; i < 4; i++) {
        float rs = acc[i][0] * acc[i][0] + acc[i][1] * acc[i][1]
                 + acc[i][2] * acc[i][2] + acc[i][3] * acc[i][3];
#pragma unroll
        for (int off = 1; off < 16; off <<= 1)
            rs += __shfl_xor_sync(0xffffffffu, rs, off);
        float inv = 1.0f / fmaxf(sqrtf(rs), 1e-12f);

        int row = rbase + ty * 4 + i;
        __half h[4], l[4];
#pragma unroll
        for (int j = 0; j < 4; j++) {
            float v = acc[i][j] * inv;
            h[j] = __float2half(v);
            l[j] = __float2half(v - __half2float(h[j]));
        }
        uint2 hp, lp;
        hp.x = ((uint32_t)__half_as_ushort(h[1]) << 16) | __half_as_ushort(h[0]);
        hp.y = ((uint32_t)__half_as_ushort(h[3]) << 16) | __half_as_ushort(h[2]);
        lp.x = ((uint32_t)__half_as_ushort(l[1]) << 16) | __half_as_ushort(l[0]);
        lp.y = ((uint32_t)__half_as_ushort(l[3]) << 16) | __half_as_ushort(l[2]);
        *reinterpret_cast<uint2*>(&out[(size_t)row * KC + tx * 4])      = hp;
        *reinterpret_cast<uint2*>(&out[(size_t)row * KC + 64 + tx * 4]) = lp;
    }
}

// ---------------------------------------------------------------------------
// scores GEMM: 128x64 tile/CTA. K=128 fp16 [hi|lo] loaded once (48KB smem).
// hi*hi -> f32 accum;  hi*lo + lo*hi -> f16 accum (magnitude ~2^-12).
// (R12 verbatim.)
// ---------------------------------------------------------------------------
__global__ __launch_bounds__(256, 2) void scores_mma_kernel(const float* __restrict__ log_scale,
                                                            float* __restrict__ out)
{
    __shared__ char smem[49152];
    const uint32_t sA = smem_u32(smem);     // 32KB: 256 swizzle-rows of 128B
    const uint32_t sB = sA + 32768;         // 16KB: 128 swizzle-rows

    const int tid  = threadIdx.x;
    const int wid  = tid >> 5;
    const int lane = tid & 31;
    const int wm = wid & 3;        // 4 warps along M (32 each)
    const int wn = wid >> 2;       // 2 warps along N (32 each)
    const int brow = blockIdx.y * 128;
    const int bcol = blockIdx.x * 64;

    const char* gA = reinterpret_cast<const char*>(g_sub_cat);
    const char* gB = reinterpret_cast<const char*>(g_edge_cat);

#pragma unroll
    for (int it = 0; it < 8; it++) {
        int qi = tid + it * 256;
        int sr = qi >> 3, lq = qi & 7;
        int r = sr & 127, c = sr >> 7;
        cpa16(sA + sr * 128 + ((lq ^ (sr & 7)) << 4),
              gA + (size_t)(brow + r) * 256 + c * 128 + lq * 16);
    }
#pragma unroll
    for (int it = 0; it < 4; it++) {
        int qi = tid + it * 256;
        int sr = qi >> 3, lq = qi & 7;
        int r = sr & 63, c = sr >> 6;
        cpa16(sB + sr * 128 + ((lq ^ (sr & 7)) << 4),
              gB + (size_t)(bcol + r) * 256 + c * 128 + lq * 16);
    }
    asm volatile("cp.async.commit_group;" ::: "memory");
    asm volatile("cp.async.wait_group 0;" ::: "memory");
    __syncthreads();

    float    accf[2][4][4];
    uint32_t acch[2][4][2];
#pragma unroll
    for (int mt = 0; mt < 2; mt++)
#pragma unroll
        for (int nt = 0; nt < 4; nt++) {
#pragma unroll
            for (int q = 0; q < 4; q++) accf[mt][nt][q] = 0.f;
            acch[mt][nt][0] = 0u; acch[mt][nt][1] = 0u;
        }

    const int g  = lane >> 3;
    const int rl = lane & 7;
    const int gl = g & 1;
    const int gh = g >> 1;

    uint32_t aOff[2][2];   // [chunk][mt]
#pragma unroll
    for (int ca = 0; ca < 2; ca++)
#pragma unroll
        for (int mt = 0; mt < 2; mt++)
            aOff[ca][mt] = sA + (uint32_t)(ca * 128 + wm * 32 + mt * 16 + rl + gl * 8) * 128u;
    uint32_t bOff[2][2];   // [chunk][pn]
#pragma unroll
    for (int cb = 0; cb < 2; cb++)
#pragma unroll
        for (int pn = 0; pn < 2; pn++)
            bOff[cb][pn] = sB + (uint32_t)(cb * 64 + wn * 32 + pn * 16 + rl + gh * 8) * 128u;

#pragma unroll
    for (int s = 0; s < 4; s++) {
        const uint32_t ca_col = (uint32_t)(((2 * s + gh) ^ rl) << 4);
        const uint32_t cb_col = (uint32_t)(((2 * s + gl) ^ rl) << 4);
        uint32_t a0[2][4], a1[2][4], b0[2][4], b1[2][4];
#pragma unroll
        for (int mt = 0; mt < 2; mt++) {
            ldmx4(a0[mt], aOff[0][mt] + ca_col);   // hi
            ldmx4(a1[mt], aOff[1][mt] + ca_col);   // lo
        }
#pragma unroll
        for (int pn = 0; pn < 2; pn++) {
            ldmx4(b0[pn], bOff[0][pn] + cb_col);   // hi
            ldmx4(b1[pn], bOff[1][pn] + cb_col);   // lo
        }
#pragma unroll
        for (int mt = 0; mt < 2; mt++)
#pragma unroll
            for (int pn = 0; pn < 2; pn++) {
                mma_f32(accf[mt][2 * pn],     a0[mt], &b0[pn][0]);
                mma_f32(accf[mt][2 * pn + 1], a0[mt], &b0[pn][2]);
                mma_f16(acch[mt][2 * pn],     a0[mt], &b1[pn][0]);
                mma_f16(acch[mt][2 * pn + 1], a0[mt], &b1[pn][2]);
                mma_f16(acch[mt][2 * pn],     a1[mt], &b0[pn][0]);
                mma_f16(acch[mt][2 * pn + 1], a1[mt], &b0[pn][2]);
            }
    }

    const float zs = 0.5f * fminf(fmaxf(expf(*log_scale), 0.5f), 20.0f);

    const int r0 = brow + wm * 32 + (lane >> 2);
    const int c0 = bcol + wn * 32 + 2 * (lane & 3);
#pragma unroll
    for (int mt = 0; mt < 2; mt++)
#pragma unroll
        for (int nt = 0; nt < 4; nt++) {
            float2 c01 = __half22float2(*reinterpret_cast<__half2*>(&acch[mt][nt][0]));
            float2 c23 = __half22float2(*reinterpret_cast<__half2*>(&acch[mt][nt][1]));
            float* p0 = out + (size_t)(r0 + mt * 16) * NE + c0 + nt * 8;
            float* p1 = p0 + 8 * NE;
            *reinterpret_cast<float2*>(p0) =
                make_float2((accf[mt][nt][0] + c01.x) * zs, (accf[mt][nt][1] + c01.y) * zs);
            *reinterpret_cast<float2*>(p1) =
                make_float2((accf[mt][nt][2] + c23.x) * zs, (accf[mt][nt][3] + c23.y) * zs);
        }
}

// ---------------------------------------------------------------------------
// entmax-1.5 per row, in place. R14 version (best measured): pass 0
// support-quadratic jump from tau0=max-1, then secant on h(tau)=sqrt(S2)-1
// (only S2 per pass), stopping at |h| < 2e-5 (||dp|| <= 4e-5, 25x margin).
// ---------------------------------------------------------------------------
__global__ __launch_bounds__(256) void entmax_kernel(float* __restrict__ out)
{
    __shared__ float s1[8], s2[2][8], sc[8], smax[8];

    const int tid  = threadIdx.x;
    const int lane = tid & 31;
    const int warp = tid >> 5;
    float4* row = reinterpret_cast<float4*>(out + (size_t)blockIdx.x * NE);

    float4 v[8];
#pragma unroll
    for (int j = 0; j < 8; j++) v[j] = row[tid + 256 * j];

    float m = -3.4e38f;
#pragma unroll
    for (int j = 0; j < 8; j++)
        m = fmaxf(m, fmaxf(fmaxf(v[j].x, v[j].y), fmaxf(v[j].z, v[j].w)));
#pragma unroll
    for (int off = 16; off > 0; off >>= 1)
        m = fmaxf(m, __shfl_xor_sync(0xffffffffu, m, off));
    if (lane == 0) smax[warp] = m;
    __syncthreads();
    float mm = smax[0];
#pragma unroll
    for (int w = 1; w < 8; w++) mm = fmaxf(mm, smax[w]);

    const float tlo = mm - 1.0f;
    const float thi = mm - 0.011048543f;   // tau* <= max - 1/sqrt(8192)
    float tau = tlo;
    float t_prev = tlo, h_prev = 0.f;

    // ---- pass 0: (S1, S2, C) at tau0; support-quadratic jump; record h0
    {
        float a = 0.f, q = 0.f, cn = 0.f;
#pragma unroll
        for (int j = 0; j < 8; j++) {
            float d;
            d = v[j].x - tau; if (d > 0.f) { a += d; q = fmaf(d, d, q); cn += 1.f; }
            d = v[j].y - tau; if (d > 0.f) { a += d; q = fmaf(d, d, q); cn += 1.f; }
            d = v[j].z - tau; if (d > 0.f) { a += d; q = fmaf(d, d, q); cn += 1.f; }
            d = v[j].w - tau; if (d > 0.f) { a += d; q = fmaf(d, d, q); cn += 1.f; }
        }
#pragma unroll
        for (int off = 16; off > 0; off >>= 1) {
            a  += __shfl_xor_sync(0xffffffffu, a,  off);
            q  += __shfl_xor_sync(0xffffffffu, q,  off);
            cn += __shfl_xor_sync(0xffffffffu, cn, off);
        }
        if (lane == 0) { s1[warp] = a; s2[0][warp] = q; sc[warp] = cn; }
        __syncthreads();
        float S1 = 0.f, S2 = 0.f, C = 0.f;
#pragma unroll
        for (int w = 0; w < 8; w++) { S1 += s1[w]; S2 += s2[0][w]; C += sc[w]; }
        h_prev = sqrtf(S2) - 1.0f;
        if (C >= 1.f && S1 > 0.f && h_prev > 1e-7f) {
            float err  = S2 - 1.0f;
            float disc = S1 * S1 - C * err;
            float dt   = (disc > 0.f) ? (S1 - sqrtf(disc)) / C
                                      : (S2 - sqrtf(S2)) / S1;
            tau = fminf(tau + dt, thi);
        }
    }

    // ---- secant on h(tau) = sqrt(S2(tau)) - 1 (only S2 per pass)
#pragma unroll 1
    for (int it = 1; it < 24; it++) {
        const int p = it & 1;
        float q = 0.f;
#pragma unroll
        for (int j = 0; j < 8; j++) {
            float d;
            d = fmaxf(v[j].x - tau, 0.f); q = fmaf(d, d, q);
            d = fmaxf(v[j].y - tau, 0.f); q = fmaf(d, d, q);
            d = fmaxf(v[j].z - tau, 0.f); q = fmaf(d, d, q);
            d = fmaxf(v[j].w - tau, 0.f); q = fmaf(d, d, q);
        }
#pragma unroll
        for (int off = 16; off > 0; off >>= 1)
            q += __shfl_xor_sync(0xffffffffu, q, off);
        if (lane == 0) s2[p][warp] = q;
        __syncthreads();
        float S2 = 0.f;
#pragma unroll
        for (int w = 0; w < 8; w++) S2 += s2[p][w];

        float h = sqrtf(S2) - 1.0f;
        if (fabsf(h) < 2e-5f) break;
        float denom = h - h_prev;
        if (fabsf(denom) < 1e-12f) break;
        float dt = -h * (tau - t_prev) / denom;
        t_prev = tau; h_prev = h;
        tau = fminf(fmaxf(tau + dt, tlo), thi);
        if (fabsf(dt) < 1e-6f) break;
    }

#pragma unroll
    for (int j = 0; j < 8; j++) {
        float4 o;
        float d;
        d = fmaxf(v[j].x - tau, 0.f); o.x = d * d;
        d = fmaxf(v[j].y - tau, 0.f); o.y = d * d;
        d = fmaxf(v[j].z - tau, 0.f); o.z = d * d;
        d = fmaxf(v[j].w - tau, 0.f); o.w = d * d;
        row[tid + 256 * j] = o;
    }
}

// ---------------------------------------------------------------------------
extern "C" void kernel_launch(void* const* d_in, const int* in_sizes, int n_in,
                              void* d_out, int out_size)
{
    const float* edge_repr = (const float*)d_in[0];
    const float* sub_repr  = (const float*)d_in[1];
    const float* W_sub     = (const float*)d_in[2];
    const float* b_sub     = (const float*)d_in[3];
    const float* W_edge    = (const float*)d_in[4];
    const float* b_edge    = (const float*)d_in[5];
    const float* log_scale = (const float*)d_in[6];
    float* out = (float*)d_out;

    proj_kernel<<<dim3(NS / 64, 2), 256>>>(sub_repr, edge_repr,
                                           W_sub, b_sub, W_edge, b_edge);

    dim3 grid(NE / 64, NS / 128);
    scores_mma_kernel<<<grid, 256>>>(log_scale, out);

    entmax_kernel<<<NS, 256>>>(out);
}